// round 4
// baseline (speedup 1.0000x reference)
#include <cuda_runtime.h>
#include <math.h>

// Problem constants (LocalRNN: B=16, L=1024, D=256, ksize=16)
#define B_   16
#define L_   1024
#define D_   256
#define KS_  16
#define G_   768            // 3*D
#define NCH_ (B_ * L_)      // 16384 chains

// Scratch for precomputed input gates: gi[n][g], n in [0,16384), g in [0,768)
__device__ float g_gi[(size_t)NCH_ * G_];   // 50.3 MB, static device scratch

// ---------------------------------------------------------------------------
// Kernel 1: GI = x @ W_ih^T + b_ih      (16384 x 768 GEMM, K=256)
// Tile 64(M) x 64(N), K-chunks of 16, TM=TN=4 register tile.
// ---------------------------------------------------------------------------
__global__ __launch_bounds__(256) void gi_gemm_kernel(
    const float* __restrict__ x,
    const float* __restrict__ Wih,
    const float* __restrict__ bih)
{
    __shared__ float As[16][68];
    __shared__ float Bs[16][68];

    const int mt  = blockIdx.x * 64;   // chain tile
    const int nt  = blockIdx.y * 64;   // gate tile
    const int tid = threadIdx.x;
    const int txx = tid & 15;          // -> j0 = txx*4
    const int tyy = tid >> 4;          // -> m0 = tyy*4

    float acc[4][4];
#pragma unroll
    for (int i = 0; i < 4; i++)
#pragma unroll
        for (int j = 0; j < 4; j++) acc[i][j] = 0.f;

    for (int kt = 0; kt < D_; kt += 16) {
#pragma unroll
        for (int i = 0; i < 4; i++) {
            int idx = i * 256 + tid;
            int m = idx >> 4, k = idx & 15;
            As[k][m] = x[(size_t)(mt + m) * D_ + kt + k];
            Bs[k][m] = Wih[(size_t)(nt + m) * D_ + kt + k];
        }
        __syncthreads();
#pragma unroll
        for (int k = 0; k < 16; k++) {
            float a[4], b[4];
#pragma unroll
            for (int i = 0; i < 4; i++) a[i] = As[k][tyy * 4 + i];
#pragma unroll
            for (int i = 0; i < 4; i++) b[i] = Bs[k][txx * 4 + i];
#pragma unroll
            for (int i = 0; i < 4; i++)
#pragma unroll
                for (int j = 0; j < 4; j++)
                    acc[i][j] = fmaf(a[i], b[j], acc[i][j]);
        }
        __syncthreads();
    }

#pragma unroll
    for (int i = 0; i < 4; i++) {
        int n = mt + tyy * 4 + i;
#pragma unroll
        for (int j = 0; j < 4; j++) {
            int g = nt + txx * 4 + j;
            g_gi[(size_t)n * G_ + g] = acc[i][j] + bih[g];
        }
    }
}

// ---------------------------------------------------------------------------
// Kernel 2: persistent GRU recurrence.
// Each CTA owns 64 consecutive chains for all 16 steps.
// Per step, per gate block g in {r,z,n}:
//   GH[64][256] = H[64][256] @ W_hh[g*256 : (g+1)*256, :]^T   (reg-tiled fp32)
// followed by a fused gate epilogue. H, R, Z tiles in smem; W_hh streamed
// from L2 in 16-wide K slices; gi rows read from g_gi (L2-resident).
//
// Dynamic smem layout (floats):
//   Hs [64*256]        @ 0
//   Rs [64*256]        @ 16384
//   Zs [64*256]        @ 32768
//   Ws [16][260]       @ 49152   (row stride 260 keeps 16B alignment)
//   bih[768]           @ 53312
//   bhh[768]           @ 54080
// total 54848 floats = 219392 B
// ---------------------------------------------------------------------------
#define WS_STRIDE 260
#define RNN_SMEM_FLOATS (49152 + 16 * WS_STRIDE + 768 + 768)
#define RNN_SMEM_BYTES  (RNN_SMEM_FLOATS * 4)

__global__ __launch_bounds__(256, 1) void rnn_kernel(
    const float* __restrict__ Whh,
    const float* __restrict__ bih_g,
    const float* __restrict__ bhh_g,
    float* __restrict__ out)
{
    extern __shared__ float sm[];
    float* Hs  = sm;
    float* Rs  = sm + 16384;
    float* Zs  = sm + 32768;
    float* Ws  = sm + 49152;
    float* bih = sm + 49152 + 16 * WS_STRIDE;
    float* bhh = bih + 768;

    const int tid  = threadIdx.x;
    const int lane = tid & 31;     // j tile: j0 = lane*8   (256 cols)
    const int wrp  = tid >> 5;     // m tile: m0 = wrp*8    (64 rows)
    const int j0   = lane * 8;
    const int m0   = wrp * 8;
    const int n0   = blockIdx.x * 64;

    for (int i = tid; i < 16384; i += 256) Hs[i] = 0.f;
    for (int i = tid; i < 768; i += 256) { bih[i] = bih_g[i]; bhh[i] = bhh_g[i]; }
    __syncthreads();

    for (int t = 0; t < KS_; t++) {
        for (int g = 0; g < 3; g++) {
            float acc[8][8];
#pragma unroll
            for (int i = 0; i < 8; i++)
#pragma unroll
                for (int j = 0; j < 8; j++) acc[i][j] = 0.f;

            const float* Wg = Whh + (size_t)g * 256 * D_;

            for (int kt = 0; kt < D_; kt += 16) {
                // Stage W slice: Ws[k][j] = Wg[j][kt+k], j = tid (256 rows)
                const float4* src = (const float4*)(Wg + (size_t)tid * D_ + kt);
#pragma unroll
                for (int i = 0; i < 4; i++) {
                    float4 v = src[i];
                    Ws[(i * 4 + 0) * WS_STRIDE + tid] = v.x;
                    Ws[(i * 4 + 1) * WS_STRIDE + tid] = v.y;
                    Ws[(i * 4 + 2) * WS_STRIDE + tid] = v.z;
                    Ws[(i * 4 + 3) * WS_STRIDE + tid] = v.w;
                }
                __syncthreads();
#pragma unroll
                for (int k = 0; k < 16; k++) {
                    float4 b0 = *(const float4*)(Ws + k * WS_STRIDE + j0);
                    float4 b1 = *(const float4*)(Ws + k * WS_STRIDE + j0 + 4);
                    float b[8] = {b0.x, b0.y, b0.z, b0.w, b1.x, b1.y, b1.z, b1.w};
                    float a[8];
#pragma unroll
                    for (int i = 0; i < 8; i++)
                        a[i] = Hs[(m0 + i) * 256 + kt + k];   // broadcast across lanes
#pragma unroll
                    for (int i = 0; i < 8; i++)
#pragma unroll
                        for (int j = 0; j < 8; j++)
                            acc[i][j] = fmaf(a[i], b[j], acc[i][j]);
                }
                __syncthreads();
            }

            // Fused gate epilogue (each thread owns its (m,j) cells across all
            // three gate blocks, so R/Z need no cross-thread sync; H writes in
            // g==2 are ordered vs. next GEMM reads by the staging barrier).
            const int gb = g * 256;
#pragma unroll
            for (int i = 0; i < 8; i++) {
                const int m  = m0 + i;
                const int n  = n0 + m;
                const int l  = n & (L_ - 1);
                const int lp = l - (KS_ - 1) + t;           // source seq position
                const float* girow = (lp >= 0)
                    ? (g_gi + (size_t)(n - (KS_ - 1) + t) * G_ + gb)
                    : (bih + gb);                            // zero-padded x -> gi = b_ih
#pragma unroll
                for (int j = 0; j < 8; j++) {
                    const int d  = j0 + j;
                    float giv = girow[d];
                    float ghv = acc[i][j] + bhh[gb + d];
                    if (g == 0) {
                        Rs[m * 256 + d] = 1.f / (1.f + expf(-(giv + ghv)));
                    } else if (g == 1) {
                        Zs[m * 256 + d] = 1.f / (1.f + expf(-(giv + ghv)));
                    } else {
                        float r  = Rs[m * 256 + d];
                        float nv = tanhf(giv + r * ghv);
                        float z  = Zs[m * 256 + d];
                        float h  = Hs[m * 256 + d];
                        Hs[m * 256 + d] = (1.f - z) * nv + z * h;
                    }
                }
            }
        }
    }

    __syncthreads();
    // Hs is densely packed [m][d] with stride 256 -> contiguous store
    for (int i = tid; i < 64 * 256; i += 256)
        out[(size_t)n0 * 256 + i] = Hs[i];
}

// ---------------------------------------------------------------------------
// Launch
// ---------------------------------------------------------------------------
extern "C" void kernel_launch(void* const* d_in, const int* in_sizes, int n_in,
                              void* d_out, int out_size)
{
    const float* x    = (const float*)d_in[0];
    const float* Wih  = (const float*)d_in[1];
    const float* Whh  = (const float*)d_in[2];
    const float* bih  = (const float*)d_in[3];
    const float* bhh  = (const float*)d_in[4];
    // d_in[5] = ksize (compile-time 16)
    float* out = (float*)d_out;

    dim3 grid1(NCH_ / 64, G_ / 64);
    gi_gemm_kernel<<<grid1, 256>>>(x, Wih, bih);

    cudaFuncSetAttribute(rnn_kernel,
                         cudaFuncAttributeMaxDynamicSharedMemorySize,
                         RNN_SMEM_BYTES);
    rnn_kernel<<<NCH_ / 64, 256, RNN_SMEM_BYTES>>>(Whh, bih, bhh, out);
}

// round 6
// speedup vs baseline: 3.4618x; 3.4618x over previous
#include <cuda_runtime.h>
#include <stdint.h>
#include <math.h>

// LocalRNN: B=16, L=1024, D=256, ksize=16
#define B_   16
#define L_   1024
#define D_   256
#define KS_  16
#define G_   768
#define NCH_ (B_ * L_)

// Static device scratch
__device__ float    g_gi[(size_t)NCH_ * G_];          // gi[chain][gate_dim], 50.3 MB
__device__ uint32_t g_wt[(size_t)256 * G_];           // Wt[k][gate_dim], tf32 bits, 768 KB
__device__ float    g_hnew[(size_t)128 * 128 * D_];   // per-CTA new-h scratch, 16.8 MB

__device__ __forceinline__ float fsig(float x)   { return __fdividef(1.f, 1.f + __expf(-x)); }
__device__ __forceinline__ float ftanhf(float x) { return __fdividef(2.f, 1.f + __expf(-2.f * x)) - 1.f; }

__device__ __forceinline__ void mma8(float* d, const uint32_t* a, uint32_t b0, uint32_t b1) {
    asm volatile(
        "mma.sync.aligned.m16n8k8.row.col.f32.tf32.tf32.f32 "
        "{%0,%1,%2,%3}, {%4,%5,%6,%7}, {%8,%9}, {%0,%1,%2,%3};"
        : "+f"(d[0]), "+f"(d[1]), "+f"(d[2]), "+f"(d[3])
        : "r"(a[0]), "r"(a[1]), "r"(a[2]), "r"(a[3]), "r"(b0), "r"(b1));
}

// ---------------------------------------------------------------------------
// Prep: Wt[k][gdim] = tf32_rna(W_hh[gdim][k])
// ---------------------------------------------------------------------------
__global__ void wprep_kernel(const float* __restrict__ Whh) {
    int e = blockIdx.x * 256 + threadIdx.x;
    if (e >= 256 * G_) return;
    int k = e & 255, gd = e >> 8;
    uint32_t v;
    asm("cvt.rna.tf32.f32 %0, %1;" : "=r"(v) : "f"(Whh[(size_t)gd * D_ + k]));
    g_wt[(size_t)k * G_ + gd] = v;
}

// ---------------------------------------------------------------------------
// gi = x @ W_ih^T + b_ih  (fp32 SIMT, known good; gi[chain][gate_dim])
// ---------------------------------------------------------------------------
__global__ __launch_bounds__(256) void gi_gemm_kernel(
    const float* __restrict__ x,
    const float* __restrict__ Wih,
    const float* __restrict__ bih)
{
    __shared__ float As[16][68];
    __shared__ float Bs[16][68];

    const int mt  = blockIdx.x * 64;
    const int nt  = blockIdx.y * 64;
    const int tid = threadIdx.x;
    const int txx = tid & 15;
    const int tyy = tid >> 4;

    float acc[4][4];
#pragma unroll
    for (int i = 0; i < 4; i++)
#pragma unroll
        for (int j = 0; j < 4; j++) acc[i][j] = 0.f;

    for (int kt = 0; kt < D_; kt += 16) {
#pragma unroll
        for (int i = 0; i < 4; i++) {
            int idx = i * 256 + tid;
            int m = idx >> 4, k = idx & 15;
            As[k][m] = x[(size_t)(mt + m) * D_ + kt + k];
            Bs[k][m] = Wih[(size_t)(nt + m) * D_ + kt + k];
        }
        __syncthreads();
#pragma unroll
        for (int k = 0; k < 16; k++) {
            float a[4], b[4];
#pragma unroll
            for (int i = 0; i < 4; i++) a[i] = As[k][tyy * 4 + i];
#pragma unroll
            for (int i = 0; i < 4; i++) b[i] = Bs[k][txx * 4 + i];
#pragma unroll
            for (int i = 0; i < 4; i++)
#pragma unroll
                for (int j = 0; j < 4; j++)
                    acc[i][j] = fmaf(a[i], b[j], acc[i][j]);
        }
        __syncthreads();
    }

#pragma unroll
    for (int i = 0; i < 4; i++) {
        int n = mt + tyy * 4 + i;
#pragma unroll
        for (int j = 0; j < 4; j++) {
            int g = nt + txx * 4 + j;
            g_gi[(size_t)n * G_ + g] = acc[i][j] + bih[g];
        }
    }
}

// ---------------------------------------------------------------------------
// Main recurrence: tf32 mma.sync. 128 CTAs x 128 chains, 8 warps (4M x 2N).
// SMEM floats: Hs[128][260] @0 (33280) | Ws 3*64*72 @33280 (13824)
//              bih @47104 (768) | bhh @47872 (768)  -> 48640 floats = 194560 B
// Per step: 4 chunks (32 dims per warp-col); per chunk: 4 K-quarters of 64;
// stage W slice [64k x 64cols x 3gates] -> mma -> fused epilogue (r,z,n,h).
// New h -> gmem scratch; copy-back with tf32 rounding (visible after
// __syncthreads per CUDA memory model for intra-block global accesses).
// ---------------------------------------------------------------------------
#define HS_STRIDE 260
#define WS_STRIDE 72
#define SMF_WS   33280
#define SMF_BIH  (SMF_WS + 3 * 64 * WS_STRIDE)
#define SMF_BHH  (SMF_BIH + G_)
#define RNN_SMEM_BYTES ((SMF_BHH + G_) * 4)

__global__ __launch_bounds__(256, 1) void rnn_mma_kernel(
    const float* __restrict__ bih_g,
    const float* __restrict__ bhh_g,
    float* __restrict__ out)
{
    extern __shared__ float sm[];
    float*    Hs   = sm;
    uint32_t* Hs_u = (uint32_t*)sm;
    uint32_t* Ws_u = (uint32_t*)(sm + SMF_WS);
    float*    bih_s = sm + SMF_BIH;
    float*    bhh_s = sm + SMF_BHH;

    const int tid  = threadIdx.x;
    const int lane = tid & 31;
    const int wid  = tid >> 5;
    const int mbase = (wid & 3) * 32;   // 32 chain-rows per M-group
    const int ncol  = wid >> 2;         // dim half: 0 -> [0,128), 1 -> [128,256)
    const int n0    = blockIdx.x * 128;
    const int qrow = lane >> 2, qcol = lane & 3;

    for (int i = tid; i < 128 * HS_STRIDE; i += 256) Hs[i] = 0.f;
    for (int i = tid; i < G_; i += 256) { bih_s[i] = bih_g[i]; bhh_s[i] = bhh_g[i]; }
    __syncthreads();

    for (int t = 0; t < KS_; t++) {
        for (int c = 0; c < 4; c++) {
            float acc[3][2][4][4];
#pragma unroll
            for (int g = 0; g < 3; g++)
#pragma unroll
                for (int mt = 0; mt < 2; mt++)
#pragma unroll
                    for (int nt = 0; nt < 4; nt++)
#pragma unroll
                        for (int e = 0; e < 4; e++) acc[g][mt][nt][e] = 0.f;

            for (int kq = 0; kq < 4; kq++) {
                __syncthreads();
                // stage W slice: 3 gates x 64 k-rows x 64 cols (both dim halves)
#pragma unroll
                for (int g = 0; g < 3; g++) {
#pragma unroll
                    for (int it = 0; it < 16; it++) {
                        int e = it * 256 + tid;            // 4096 elems
                        int k = e >> 6, j = e & 63;
                        int dim = c * 32 + ((j & 32) << 2) + (j & 31); // j<32: c*32+j ; j>=32: 128+c*32+(j-32)
                        Ws_u[g * (64 * WS_STRIDE) + k * WS_STRIDE + j] =
                            g_wt[(size_t)(kq * 64 + k) * G_ + g * 256 + dim];
                    }
                }
                __syncthreads();

#pragma unroll 2
                for (int k8 = 0; k8 < 8; k8++) {
                    const int kk = kq * 64 + k8 * 8 + qcol;
                    uint32_t a[2][4];
#pragma unroll
                    for (int mt = 0; mt < 2; mt++) {
                        const int r = mbase + mt * 16 + qrow;
                        a[mt][0] = Hs_u[r * HS_STRIDE + kk];
                        a[mt][1] = Hs_u[(r + 8) * HS_STRIDE + kk];
                        a[mt][2] = Hs_u[r * HS_STRIDE + kk + 4];
                        a[mt][3] = Hs_u[(r + 8) * HS_STRIDE + kk + 4];
                    }
#pragma unroll
                    for (int g = 0; g < 3; g++) {
                        const uint32_t* wb = Ws_u + g * (64 * WS_STRIDE)
                                           + (k8 * 8 + qcol) * WS_STRIDE + ncol * 32 + qrow;
#pragma unroll
                        for (int nt = 0; nt < 4; nt++) {
                            const uint32_t b0 = wb[nt * 8];
                            const uint32_t b1 = wb[4 * WS_STRIDE + nt * 8];
                            mma8(acc[g][0][nt], a[0], b0, b1);
                            mma8(acc[g][1][nt], a[1], b0, b1);
                        }
                    }
                }
            }

            // ---- fused epilogue for this chunk's 32 dims (per warp-col) ----
            const int dbase = ncol * 128 + c * 32 + 2 * qcol;
#pragma unroll
            for (int nt = 0; nt < 4; nt++) {
                const int dwg = dbase + nt * 8;
                const float2 bhr = *(const float2*)(bhh_s + dwg);
                const float2 bhz = *(const float2*)(bhh_s + 256 + dwg);
                const float2 bhn = *(const float2*)(bhh_s + 512 + dwg);
#pragma unroll
                for (int mt = 0; mt < 2; mt++) {
#pragma unroll
                    for (int eh = 0; eh < 2; eh++) {
                        const int row   = mbase + mt * 16 + eh * 8 + qrow;
                        const int chain = n0 + row;
                        const int lp    = (chain & (L_ - 1)) - (KS_ - 1) + t;
                        float2 gr, gz, gn;
                        if (lp >= 0) {
                            const float* gp = g_gi + (size_t)(chain - (KS_ - 1) + t) * G_;
                            gr = *(const float2*)(gp + dwg);
                            gz = *(const float2*)(gp + 256 + dwg);
                            gn = *(const float2*)(gp + 512 + dwg);
                        } else {
                            gr = *(const float2*)(bih_s + dwg);
                            gz = *(const float2*)(bih_s + 256 + dwg);
                            gn = *(const float2*)(bih_s + 512 + dwg);
                        }
                        float2 hv;
#pragma unroll
                        for (int e2 = 0; e2 < 2; e2++) {
                            const float ghr = acc[0][mt][nt][eh * 2 + e2] + (e2 ? bhr.y : bhr.x);
                            const float ghz = acc[1][mt][nt][eh * 2 + e2] + (e2 ? bhz.y : bhz.x);
                            const float ghn = acc[2][mt][nt][eh * 2 + e2] + (e2 ? bhn.y : bhn.x);
                            const float gir = e2 ? gr.y : gr.x;
                            const float giz = e2 ? gz.y : gz.x;
                            const float gin = e2 ? gn.y : gn.x;
                            const float rg = fsig(gir + ghr);
                            const float zg = fsig(giz + ghz);
                            const float ng = ftanhf(gin + rg * ghn);
                            const float ho = Hs[row * HS_STRIDE + dwg + e2];
                            (e2 ? hv.y : hv.x) = (1.f - zg) * ng + zg * ho;
                        }
                        if (t == KS_ - 1)
                            *(float2*)(out + (size_t)chain * D_ + dwg) = hv;
                        else
                            *(float2*)(g_hnew + ((size_t)blockIdx.x * 128 + row) * D_ + dwg) = hv;
                    }
                }
            }
        }

        if (t < KS_ - 1) {
            __syncthreads();   // all epilogue gmem writes by this block now visible to it
            const float* src = g_hnew + (size_t)blockIdx.x * 128 * D_;
            for (int i = tid; i < 128 * D_; i += 256) {
                uint32_t v;
                asm("cvt.rna.tf32.f32 %0, %1;" : "=r"(v) : "f"(src[i]));
                Hs_u[(i >> 8) * HS_STRIDE + (i & 255)] = v;
            }
            __syncthreads();
        }
    }
}

// ---------------------------------------------------------------------------
// Launch
// ---------------------------------------------------------------------------
extern "C" void kernel_launch(void* const* d_in, const int* in_sizes, int n_in,
                              void* d_out, int out_size)
{
    const float* x   = (const float*)d_in[0];
    const float* Wih = (const float*)d_in[1];
    const float* Whh = (const float*)d_in[2];
    const float* bih = (const float*)d_in[3];
    const float* bhh = (const float*)d_in[4];
    float* out = (float*)d_out;

    wprep_kernel<<<768, 256>>>(Whh);

    dim3 gi_grid(NCH_ / 64, G_ / 64);
    gi_gemm_kernel<<<gi_grid, 256>>>(x, Wih, bih);

    cudaFuncSetAttribute(rnn_mma_kernel,
                         cudaFuncAttributeMaxDynamicSharedMemorySize,
                         RNN_SMEM_BYTES);
    rnn_mma_kernel<<<128, 256, RNN_SMEM_BYTES>>>(bih, bhh, out);
}